// round 13
// baseline (speedup 1.0000x reference)
#include <cuda_runtime.h>
#include <cuda_bf16.h>
#include <math.h>
#include <stdint.h>

#define TT   2048
#define HID  2048
#define NH   16
#define NKV  8
#define HD   128
#define QKVN 4096   /* NH*HD + 2*NKV*HD */

// ---------------- scratch (device globals: alloc-free rule) ----------------
__device__ float g_qkv[(size_t)TT * QKVN];      // 32 MB
__device__ float g_att[(size_t)TT * NH * HD];   // 16 MB  (attention output)

// bf16 hi/lo split copies for tensor-core GEMMs
__device__ __nv_bfloat16 g_hid_hi[(size_t)TT * HID];
__device__ __nv_bfloat16 g_hid_lo[(size_t)TT * HID];
__device__ __nv_bfloat16 g_w1_hi [(size_t)QKVN * HID];
__device__ __nv_bfloat16 g_w1_lo [(size_t)QKVN * HID];
__device__ __nv_bfloat16 g_ow_hi [(size_t)HID * HID];
__device__ __nv_bfloat16 g_ow_lo [(size_t)HID * HID];
__device__ __nv_bfloat16 g_at_hi [(size_t)TT * HID];
__device__ __nv_bfloat16 g_at_lo [(size_t)TT * HID];

// bf16 hi/lo Q/K/V for tensor-core attention
__device__ __nv_bfloat16 g_qh[(size_t)TT * NH * HD];
__device__ __nv_bfloat16 g_ql[(size_t)TT * NH * HD];
__device__ __nv_bfloat16 g_kh[(size_t)TT * NKV * HD];
__device__ __nv_bfloat16 g_kl[(size_t)TT * NKV * HD];
__device__ __nv_bfloat16 g_vh[(size_t)TT * NKV * HD];
__device__ __nv_bfloat16 g_vl[(size_t)TT * NKV * HD];

// ======================== helpers ========================
__device__ __forceinline__ uint32_t smem_u32(const void* p) {
    uint32_t a;
    asm("{ .reg .u64 t; cvta.to.shared.u64 t, %1; cvt.u32.u64 %0, t; }"
        : "=r"(a) : "l"(p));
    return a;
}
__device__ __forceinline__ void ldmx4(uint32_t addr, uint32_t& r0, uint32_t& r1,
                                      uint32_t& r2, uint32_t& r3) {
    asm volatile("ldmatrix.sync.aligned.m8n8.x4.shared.b16 {%0,%1,%2,%3}, [%4];"
                 : "=r"(r0), "=r"(r1), "=r"(r2), "=r"(r3) : "r"(addr));
}
__device__ __forceinline__ void ldmx4t(uint32_t addr, uint32_t& r0, uint32_t& r1,
                                       uint32_t& r2, uint32_t& r3) {
    asm volatile("ldmatrix.sync.aligned.m8n8.x4.trans.shared.b16 {%0,%1,%2,%3}, [%4];"
                 : "=r"(r0), "=r"(r1), "=r"(r2), "=r"(r3) : "r"(addr));
}
__device__ __forceinline__ void mma16816(float* c, const uint32_t* a,
                                         uint32_t b0, uint32_t b1) {
    asm volatile(
        "mma.sync.aligned.m16n8k16.row.col.f32.bf16.bf16.f32 "
        "{%0,%1,%2,%3}, {%4,%5,%6,%7}, {%8,%9}, {%0,%1,%2,%3};"
        : "+f"(c[0]), "+f"(c[1]), "+f"(c[2]), "+f"(c[3])
        : "r"(a[0]), "r"(a[1]), "r"(a[2]), "r"(a[3]), "r"(b0), "r"(b1));
}
__device__ __forceinline__ void cpa16(uint32_t dst, const void* src) {
    asm volatile("cp.async.cg.shared.global [%0], [%1], 16;"
                 :: "r"(dst), "l"(src) : "memory");
}
// pack two fp32 into bf16x2: low half = e0, high half = e1
__device__ __forceinline__ uint32_t packbf16(float e0, float e1) {
    uint32_t r;
    asm("cvt.rn.bf16x2.f32 %0, %1, %2;" : "=r"(r) : "f"(e1), "f"(e0));
    return r;
}
__device__ __forceinline__ void split2(float e0, float e1, uint32_t& hi, uint32_t& lo) {
    float h0 = __bfloat162float(__float2bfloat16(e0));
    float h1 = __bfloat162float(__float2bfloat16(e1));
    hi = packbf16(h0, h1);
    lo = packbf16(e0 - h0, e1 - h1);
}

// ======================================================================
// fp32 -> bf16 hi/lo split (8 floats per thread)
// ======================================================================
__global__ __launch_bounds__(256) void cvt_hilo(
    const float* __restrict__ x, __nv_bfloat16* __restrict__ hi,
    __nv_bfloat16* __restrict__ lo, int n8)
{
    int i = blockIdx.x * 256 + threadIdx.x;
    if (i >= n8) return;
    float4 a = ((const float4*)x)[i * 2];
    float4 b = ((const float4*)x)[i * 2 + 1];
    float v[8] = {a.x, a.y, a.z, a.w, b.x, b.y, b.z, b.w};
    __nv_bfloat16 h[8], l[8];
    #pragma unroll
    for (int k = 0; k < 8; k++) {
        h[k] = __float2bfloat16(v[k]);
        l[k] = __float2bfloat16(v[k] - __bfloat162float(h[k]));
    }
    *(uint4*)(hi + (size_t)i * 8) = *(uint4*)h;
    *(uint4*)(lo + (size_t)i * 8) = *(uint4*)l;
}

// V slice (strided inside qkv) -> contiguous bf16 hi/lo [T][NKV][HD]
__global__ __launch_bounds__(256) void cvt_v(
    const float* __restrict__ qkv,
    __nv_bfloat16* __restrict__ hi, __nv_bfloat16* __restrict__ lo)
{
    int i = blockIdx.x * 256 + threadIdx.x;      // float4 index
    const int n4 = TT * NKV * HD / 4;
    if (i >= n4) return;
    int idx = i * 4;
    int row = idx / HD;                          // t*NKV + kv
    int d   = idx % HD;
    int t = row / NKV, kv = row % NKV;
    float4 v = *(const float4*)(qkv + (size_t)t * QKVN + (NH + NKV) * HD + kv * HD + d);
    float e[4] = {v.x, v.y, v.z, v.w};
    __nv_bfloat16 h[4], l[4];
    #pragma unroll
    for (int k = 0; k < 4; k++) {
        h[k] = __float2bfloat16(e[k]);
        l[k] = __float2bfloat16(e[k] - __bfloat162float(h[k]));
    }
    *(uint2*)(hi + idx) = *(uint2*)h;
    *(uint2*)(lo + idx) = *(uint2*)l;
}

// ======================================================================
// HMMA bf16-split GEMM: C[M,N] = A[M,K]*B[N,K]^T, D=Ahi*Bhi+Ahi*Blo+Alo*Bhi.
// Round 12: 4 warps x (64x64) warp tile (2x register reuse per LDS byte),
// cp.async double-buffered fills (no register staging), 128 thr, 2 CTA/SM.
// ======================================================================
#define KCH    32
#define ROWB   80
#define MATB   (128 * ROWB)
#define BUFB   (4 * MATB)

__global__ __launch_bounds__(128, 2) void gemm_hmma(
    const __nv_bfloat16* __restrict__ Ahi, const __nv_bfloat16* __restrict__ Alo,
    const __nv_bfloat16* __restrict__ Bhi, const __nv_bfloat16* __restrict__ Blo,
    float* __restrict__ C, int N, int K)
{
    extern __shared__ char smem[];
    const uint32_t sb = smem_u32(smem);
    const int tid  = threadIdx.x;
    const int wid  = tid >> 5;
    const int lane = tid & 31;
    const int bm   = blockIdx.y * 128;
    const int bn   = blockIdx.x * 128;
    const int wm   = wid & 1;            // m half: 64 rows
    const int wn   = wid >> 1;           // n half: 64 cols

    // copy mapping: thread r = tid owns one full 64B row of each matrix
    const __nv_bfloat16* src[4] = {
        Ahi + (size_t)(bm + tid) * K,
        Alo + (size_t)(bm + tid) * K,
        Bhi + (size_t)(bn + tid) * K,
        Blo + (size_t)(bn + tid) * K };
    const uint32_t stoff = (uint32_t)(tid * ROWB);

    const uint32_t arow = (uint32_t)((lane & 7) + ((lane & 8) ? 8 : 0));
    const uint32_t akb  = (lane & 16) ? 16u : 0u;
    const uint32_t brow = (uint32_t)((lane & 7) + ((lane & 16) ? 8 : 0));
    const uint32_t bkb  = (lane & 8) ? 16u : 0u;

    float acc[4][8][4];
    #pragma unroll
    for (int i = 0; i < 4; i++)
        #pragma unroll
        for (int j = 0; j < 8; j++)
            #pragma unroll
            for (int q = 0; q < 4; q++) acc[i][j][q] = 0.f;

    // preload chunk 0 into buffer 0 via cp.async
    #pragma unroll
    for (int m4 = 0; m4 < 4; m4++)
        #pragma unroll
        for (int u = 0; u < 4; u++)
            cpa16(sb + m4 * MATB + stoff + u * 16, src[m4] + u * 8);
    asm volatile("cp.async.commit_group;");
    asm volatile("cp.async.wait_group 0;");
    __syncthreads();

    const int nchunks = K / KCH;
    int cur = 0;
    for (int c = 0; c < nchunks; c++) {
        const bool have_next = (c + 1 < nchunks);
        if (have_next) {                        // prefetch into other buffer
            const int k0 = (c + 1) * KCH;
            const uint32_t nbo = sb + (uint32_t)((cur ^ 1) * BUFB);
            #pragma unroll
            for (int m4 = 0; m4 < 4; m4++)
                #pragma unroll
                for (int u = 0; u < 4; u++)
                    cpa16(nbo + m4 * MATB + stoff + u * 16, src[m4] + k0 + u * 8);
            asm volatile("cp.async.commit_group;");
        }

        const uint32_t bufo = sb + (uint32_t)(cur * BUFB);
        #pragma unroll
        for (int ks = 0; ks < 2; ks++) {
            const uint32_t kb = ks * 32;
            uint32_t ahi[4][4], alo[4][4];
            #pragma unroll
            for (int i = 0; i < 4; i++) {
                uint32_t ra = (uint32_t)(wm * 64 + i * 16) + arow;
                uint32_t ao = bufo + ra * ROWB + kb + akb;
                ldmx4(ao,        ahi[i][0], ahi[i][1], ahi[i][2], ahi[i][3]);
                ldmx4(ao + MATB, alo[i][0], alo[i][1], alo[i][2], alo[i][3]);
            }
            #pragma unroll
            for (int j = 0; j < 4; j++) {       // 4 j-tiles of 16 B-rows each
                uint32_t rb = (uint32_t)(wn * 64 + j * 16) + brow;
                uint32_t bo = bufo + 2 * MATB + rb * ROWB + kb + bkb;
                uint32_t bh0, bh1, bh2, bh3, bl0, bl1, bl2, bl3;
                ldmx4(bo,        bh0, bh1, bh2, bh3);
                ldmx4(bo + MATB, bl0, bl1, bl2, bl3);
                #pragma unroll
                for (int i = 0; i < 4; i++) {
                    mma16816(acc[i][2*j],     ahi[i], bh0, bh1);
                    mma16816(acc[i][2*j],     ahi[i], bl0, bl1);
                    mma16816(acc[i][2*j],     alo[i], bh0, bh1);
                    mma16816(acc[i][2*j + 1], ahi[i], bh2, bh3);
                    mma16816(acc[i][2*j + 1], ahi[i], bl2, bl3);
                    mma16816(acc[i][2*j + 1], alo[i], bh2, bh3);
                }
            }
        }

        if (have_next) {
            asm volatile("cp.async.wait_group 0;");
            __syncthreads();
            cur ^= 1;
        }
    }

    // epilogue: acc[i][jt]: rows bm+wm*64+i*16+{r0,r0+8}, cols bn+wn*64+jt*8+c0
    const int er = lane >> 2;
    const int ec = (lane & 3) * 2;
    #pragma unroll
    for (int i = 0; i < 4; i++) {
        const int row0 = bm + wm * 64 + i * 16 + er;
        #pragma unroll
        for (int jt = 0; jt < 8; jt++) {
            const int col = bn + wn * 64 + jt * 8 + ec;
            *(float2*)&C[(size_t)row0 * N + col]       = make_float2(acc[i][jt][0], acc[i][jt][1]);
            *(float2*)&C[(size_t)(row0 + 8) * N + col] = make_float2(acc[i][jt][2], acc[i][jt][3]);
        }
    }
}

// ======================================================================
// RMSNorm + RoPE -> bf16 hi/lo Q (pre-scaled) and K. One warp per slot.
// ======================================================================
__global__ __launch_bounds__(128) void norm_rope(
    const int* __restrict__ positions,
    const float* __restrict__ qw, const float* __restrict__ kw)
{
    const int slot = blockIdx.x * 4 + (threadIdx.x >> 5);
    const int lane = threadIdx.x & 31;
    const int t  = slot / (NH + NKV);
    const int hh = slot % (NH + NKV);
    const bool isq = hh < NH;

    const float* x = g_qkv + (size_t)t * QKVN +
                     (isq ? hh * HD : NH * HD + (hh - NH) * HD);

    float v0 = x[lane];
    float v1 = x[lane + 32];
    float v2 = x[lane + 64];
    float v3 = x[lane + 96];

    float ss = v0*v0 + v1*v1 + v2*v2 + v3*v3;
    #pragma unroll
    for (int o = 16; o; o >>= 1) ss += __shfl_xor_sync(0xffffffffu, ss, o);

    float rr = rsqrtf(ss * (1.0f / HD) + 1e-6f);
    const float* w = isq ? qw : kw;
    float x0 = v0 * rr * w[lane];
    float x1 = v1 * rr * w[lane + 32];
    float x2 = v2 * rr * w[lane + 64];
    float x3 = v3 * rr * w[lane + 96];

    const float pos = (float)positions[t];
    float f0 = 1.0f / powf(1000000.0f, (float)lane        * (1.0f / 64.0f));
    float f1 = 1.0f / powf(1000000.0f, (float)(lane + 32) * (1.0f / 64.0f));
    float s0, c0, s1, c1;
    sincosf(pos * f0, &s0, &c0);
    sincosf(pos * f1, &s1, &c1);

    const float sc = isq ? 0.08838834764831845f : 1.0f;   // fold softmax scale into Q
    float o0 = (x0 * c0 - x2 * s0) * sc;
    float o1 = (x1 * c1 - x3 * s1) * sc;
    float o2 = (x2 * c0 + x0 * s0) * sc;
    float o3 = (x3 * c1 + x1 * s1) * sc;

    size_t base = isq ? ((size_t)t * NH + hh) * HD
                      : ((size_t)t * NKV + (hh - NH)) * HD;
    __nv_bfloat16* dh = isq ? g_qh + base : g_kh + base;
    __nv_bfloat16* dl = isq ? g_ql + base : g_kl + base;

    float vv[4] = {o0, o1, o2, o3};
    int   dd[4] = {lane, lane + 32, lane + 64, lane + 96};
    #pragma unroll
    for (int k = 0; k < 4; k++) {
        __nv_bfloat16 h = __float2bfloat16(vv[k]);
        dh[dd[k]] = h;
        dl[dd[k]] = __float2bfloat16(vv[k] - __bfloat162float(h));
    }
}

// ======================================================================
// Tensor-core causal GQA flash attention (unchanged — passing round 12).
// ======================================================================
#define AMAT (64 * 272)

__global__ __launch_bounds__(128, 2) void attn_mma(
    const __nv_bfloat16* __restrict__ Qh, const __nv_bfloat16* __restrict__ Ql,
    const __nv_bfloat16* __restrict__ Kh, const __nv_bfloat16* __restrict__ Kl,
    const __nv_bfloat16* __restrict__ Vh, const __nv_bfloat16* __restrict__ Vl,
    float* __restrict__ out)
{
    extern __shared__ char sm[];
    const uint32_t s0  = smem_u32(sm);
    const uint32_t sQH = s0,            sQL = s0 + AMAT;
    const uint32_t sKH = s0 + 2 * AMAT, sKL = s0 + 3 * AMAT;
    const uint32_t sVH = s0 + 4 * AMAT, sVL = s0 + 5 * AMAT;

    const int h    = blockIdx.y;
    const int qb   = (int)gridDim.x - 1 - (int)blockIdx.x;  // heavy blocks first
    const int kvh  = h >> 1;
    const int tid  = threadIdx.x;
    const int wq   = tid >> 5;
    const int lane = tid & 31;

    const int cr  = tid >> 1;     // copy row 0..63
    const int chf = tid & 1;      // col half (64 elements = 128 bytes)

    // Q tile (hi/lo) -> smem, once: full 128B per (row, half)
    {
        size_t qoff = ((size_t)(qb * 64 + cr) * NH + h) * HD + chf * 64;
        uint32_t dh = sQH + cr * 272 + chf * 128;
        uint32_t dl = sQL + cr * 272 + chf * 128;
        #pragma unroll
        for (int u = 0; u < 8; u++) {
            cpa16(dh + u * 16, Qh + qoff + u * 8);
            cpa16(dl + u * 16, Ql + qoff + u * 8);
        }
    }
    asm volatile("cp.async.commit_group;");

    // per-lane ldmatrix offsets (bytes, within a 64x272B matrix)
    const uint32_t qoffm = (uint32_t)((wq * 16 + (lane & 15)) * 272 + ((lane & 16) ? 16 : 0));
    const uint32_t koffm = (uint32_t)((((lane & 7) + ((lane & 16) ? 8 : 0))) * 272 + ((lane & 8) ? 16 : 0));
    const uint32_t voffm = (uint32_t)((((lane & 7) + ((lane & 8) ? 8 : 0))) * 272 + ((lane & 16) ? 16 : 0));

    float O[16][4];
    #pragma unroll
    for (int i = 0; i < 16; i++)
        #pragma unroll
        for (int q = 0; q < 4; q++) O[i][q] = 0.f;
    float m0 = -1e30f, m1 = -1e30f, l0 = 0.f, l1 = 0.f;

    const int r0 = lane >> 2;
    const int c0 = (lane & 3) * 2;

    for (int kt = 0; kt <= qb; kt++) {
        __syncthreads();   // previous block's reads done
        {
            size_t base = ((size_t)(kt * 64 + cr) * NKV + kvh) * HD + chf * 64;
            uint32_t doff = cr * 272 + chf * 128;
            #pragma unroll
            for (int u = 0; u < 8; u++) {
                cpa16(sKH + doff + u * 16, Kh + base + u * 8);
                cpa16(sKL + doff + u * 16, Kl + base + u * 8);
                cpa16(sVH + doff + u * 16, Vh + base + u * 8);
                cpa16(sVL + doff + u * 16, Vl + base + u * 8);
            }
        }
        asm volatile("cp.async.commit_group;");
        asm volatile("cp.async.wait_group 0;");
        __syncthreads();

        // ---- scores S[64q x 64j] per warp: 16 x 64 ----
        float S[8][4];
        #pragma unroll
        for (int i = 0; i < 8; i++)
            #pragma unroll
            for (int q = 0; q < 4; q++) S[i][q] = 0.f;

        #pragma unroll
        for (int ks = 0; ks < 8; ks++) {
            uint32_t qh[4], ql[4];
            ldmx4(sQH + qoffm + ks * 32, qh[0], qh[1], qh[2], qh[3]);
            ldmx4(sQL + qoffm + ks * 32, ql[0], ql[1], ql[2], ql[3]);
            #pragma unroll
            for (int g = 0; g < 4; g++) {
                uint32_t ka = koffm + g * (16 * 272) + ks * 32;
                uint32_t kh0, kh1, kh2, kh3, kl0, kl1, kl2, kl3;
                ldmx4(sKH + ka, kh0, kh1, kh2, kh3);
                ldmx4(sKL + ka, kl0, kl1, kl2, kl3);
                mma16816(S[2*g],     qh, kh0, kh1);
                mma16816(S[2*g],     qh, kl0, kl1);
                mma16816(S[2*g],     ql, kh0, kh1);
                mma16816(S[2*g + 1], qh, kh2, kh3);
                mma16816(S[2*g + 1], qh, kl2, kl3);
                mma16816(S[2*g + 1], ql, kh2, kh3);
            }
        }

        // ---- causal mask (diagonal block only) ----
        if (kt == qb) {
            const int ra = wq * 16 + r0, rb = ra + 8;
            #pragma unroll
            for (int nt = 0; nt < 8; nt++) {
                int j = nt * 8 + c0;
                if (j     > ra) S[nt][0] = -1e30f;
                if (j + 1 > ra) S[nt][1] = -1e30f;
                if (j     > rb) S[nt][2] = -1e30f;
                if (j + 1 > rb) S[nt][3] = -1e30f;
            }
        }

        // ---- online softmax ----
        float mt0 = -1e30f, mt1 = -1e30f;
        #pragma unroll
        for (int nt = 0; nt < 8; nt++) {
            mt0 = fmaxf(mt0, fmaxf(S[nt][0], S[nt][1]));
            mt1 = fmaxf(mt1, fmaxf(S[nt][2], S[nt][3]));
        }
        mt0 = fmaxf(mt0, __shfl_xor_sync(0xffffffffu, mt0, 1));
        mt0 = fmaxf(mt0, __shfl_xor_sync(0xffffffffu, mt0, 2));
        mt1 = fmaxf(mt1, __shfl_xor_sync(0xffffffffu, mt1, 1));
        mt1 = fmaxf(mt1, __shfl_xor_sync(0xffffffffu, mt1, 2));

        float mn0 = fmaxf(m0, mt0), mn1 = fmaxf(m1, mt1);
        float al0 = __expf(m0 - mn0), al1 = __expf(m1 - mn1);
        m0 = mn0; m1 = mn1;

        float s0r = 0.f, s1r = 0.f;
        #pragma unroll
        for (int nt = 0; nt < 8; nt++) {
            S[nt][0] = __expf(S[nt][0] - mn0); s0r += S[nt][0];
            S[nt][1] = __expf(S[nt][1] - mn0); s0r += S[nt][1];
            S[nt][2] = __expf(S[nt][2] - mn1); s1r += S[nt][2];
            S[nt][3] = __expf(S[nt][3] - mn1); s1r += S[nt][3];
        }
        s0r += __shfl_xor_sync(0xffffffffu, s0r, 1);
        s0r += __shfl_xor_sync(0xffffffffu, s0r, 2);
        s1r += __shfl_xor_sync(0xffffffffu, s1r, 1);
        s1r += __shfl_xor_sync(0xffffffffu, s1r, 2);
        l0 = l0 * al0 + s0r;
        l1 = l1 * al1 + s1r;

        #pragma unroll
        for (int nd = 0; nd < 16; nd++) {
            O[nd][0] *= al0; O[nd][1] *= al0;
            O[nd][2] *= al1; O[nd][3] *= al1;
        }

        // ---- PV: O[16 x 128] += P[16 x 64] * V[64 x 128] ----
        #pragma unroll
        for (int g = 0; g < 4; g++) {
            uint32_t ph[4], pl[4];
            split2(S[2*g][0],     S[2*g][1],     ph[0], pl[0]);
            split2(S[2*g][2],     S[2*g][3],     ph[1], pl[1]);
            split2(S[2*g + 1][0], S[2*g + 1][1], ph[2], pl[2]);
            split2(S[2*g + 1][2], S[2*g + 1][3], ph[3], pl[3]);
            #pragma unroll
            for (int db = 0; db < 8; db++) {
                uint32_t va = voffm + g * (16 * 272) + db * 32;
                uint32_t vh0, vh1, vh2, vh3, vl0, vl1, vl2, vl3;
                ldmx4t(sVH + va, vh0, vh1, vh2, vh3);
                ldmx4t(sVL + va, vl0, vl1, vl2, vl3);
                mma16816(O[2*db],     ph, vh0, vh1);
                mma16816(O[2*db],     ph, vl0, vl1);
                mma16816(O[2*db],     pl, vh0, vh1);
                mma16816(O[2*db + 1], ph, vh2, vh3);
                mma16816(O[2*db + 1], ph, vl2, vl3);
                mma16816(O[2*db + 1], pl, vh2, vh3);
            }
        }
    }

    // ---- write out ----
    const float i0 = 1.f / l0, i1 = 1.f / l1;
    const int qg = qb * 64 + wq * 16;
    float* oa = out + (size_t)(qg + r0)     * (NH * HD) + h * HD + c0;
    float* ob = out + (size_t)(qg + r0 + 8) * (NH * HD) + h * HD + c0;
    #pragma unroll
    for (int nd = 0; nd < 16; nd++) {
        *(float2*)(oa + nd * 8) = make_float2(O[nd][0] * i0, O[nd][1] * i0);
        *(float2*)(ob + nd * 8) = make_float2(O[nd][2] * i1, O[nd][3] * i1);
    }
}

// ======================================================================
// launch — inputs bound by element count (order-agnostic)
// ======================================================================
extern "C" void kernel_launch(void* const* d_in, const int* in_sizes, int n_in,
                              void* d_out, int out_size)
{
    const float* hidden    = 0;
    const int*   positions = 0;
    const float* qkv_w     = 0;
    const float* o_w       = 0;
    const float* qw        = 0;
    const float* kw        = 0;

    for (int i = 0; i < n_in; i++) {
        int s = in_sizes[i];
        if (s == QKVN * HID)            qkv_w = (const float*)d_in[i];
        else if (s == TT * HID) {
            if (!hidden) hidden = (const float*)d_in[i];
            else         o_w    = (const float*)d_in[i];
        }
        else if (s == TT)               positions = (const int*)d_in[i];
        else if (s == HD) {
            if (!qw) qw = (const float*)d_in[i];
            else     kw = (const float*)d_in[i];
        }
    }
    if (!kw) kw = qw;

    float* out = (float*)d_out;

    float *qkv_p, *att_p;
    cudaGetSymbolAddress((void**)&qkv_p, g_qkv);
    cudaGetSymbolAddress((void**)&att_p, g_att);
    __nv_bfloat16 *hid_hi, *hid_lo, *w1_hi, *w1_lo, *ow_hi, *ow_lo, *at_hi, *at_lo;
    __nv_bfloat16 *qh, *ql, *kh, *kl, *vh, *vl;
    cudaGetSymbolAddress((void**)&hid_hi, g_hid_hi);
    cudaGetSymbolAddress((void**)&hid_lo, g_hid_lo);
    cudaGetSymbolAddress((void**)&w1_hi,  g_w1_hi);
    cudaGetSymbolAddress((void**)&w1_lo,  g_w1_lo);
    cudaGetSymbolAddress((void**)&ow_hi,  g_ow_hi);
    cudaGetSymbolAddress((void**)&ow_lo,  g_ow_lo);
    cudaGetSymbolAddress((void**)&at_hi,  g_at_hi);
    cudaGetSymbolAddress((void**)&at_lo,  g_at_lo);
    cudaGetSymbolAddress((void**)&qh, g_qh);
    cudaGetSymbolAddress((void**)&ql, g_ql);
    cudaGetSymbolAddress((void**)&kh, g_kh);
    cudaGetSymbolAddress((void**)&kl, g_kl);
    cudaGetSymbolAddress((void**)&vh, g_vh);
    cudaGetSymbolAddress((void**)&vl, g_vl);

    const int gemm_smem = 2 * BUFB;          // 81920
    cudaFuncSetAttribute(gemm_hmma,
                         cudaFuncAttributeMaxDynamicSharedMemorySize, gemm_smem);
    const int attn_smem = 6 * AMAT;          // 104448
    cudaFuncSetAttribute(attn_mma,
                         cudaFuncAttributeMaxDynamicSharedMemorySize, attn_smem);

    // 0. hi/lo splits of GEMM operands
    cvt_hilo<<<(TT * HID / 8 + 255) / 256, 256>>>(hidden, hid_hi, hid_lo, TT * HID / 8);
    cvt_hilo<<<(QKVN * HID / 8 + 255) / 256, 256>>>(qkv_w, w1_hi, w1_lo, QKVN * HID / 8);
    cvt_hilo<<<(HID * HID / 8 + 255) / 256, 256>>>(o_w, ow_hi, ow_lo, HID * HID / 8);

    // 1. QKV projection (HMMA, 64x64 warp tiles)
    gemm_hmma<<<dim3(QKVN / 128, TT / 128), 128, gemm_smem>>>(
        hid_hi, hid_lo, w1_hi, w1_lo, qkv_p, QKVN, HID);

    // 2. RMSNorm + RoPE -> bf16 hi/lo Q,K ; V split
    norm_rope<<<TT * (NH + NKV) / 4, 128>>>(positions, qw, kw);
    cvt_v<<<(TT * NKV * HD / 4 + 255) / 256, 256>>>(qkv_p, vh, vl);

    // 3. Tensor-core causal attention
    attn_mma<<<dim3(TT / 64, NH), 128, attn_smem>>>(qh, ql, kh, kl, vh, vl, att_p);

    // 4. Output projection (HMMA, 64x64 warp tiles)
    cvt_hilo<<<(TT * HID / 8 + 255) / 256, 256>>>(att_p, at_hi, at_lo, TT * HID / 8);
    gemm_hmma<<<dim3(HID / 128, TT / 128), 128, gemm_smem>>>(
        at_hi, at_lo, ow_hi, ow_lo, out, HID, HID);
}

// round 15
// speedup vs baseline: 1.1283x; 1.1283x over previous
#include <cuda_runtime.h>
#include <cuda_bf16.h>
#include <math.h>
#include <stdint.h>

#define TT   2048
#define HID  2048
#define NH   16
#define NKV  8
#define HD   128
#define QKVN 4096   /* NH*HD + 2*NKV*HD */

// ---------------- scratch (device globals: alloc-free rule) ----------------
__device__ float g_qkv[(size_t)TT * QKVN];      // 32 MB

// bf16 hi/lo split copies for tensor-core GEMMs
__device__ __nv_bfloat16 g_hid_hi[(size_t)TT * HID];
__device__ __nv_bfloat16 g_hid_lo[(size_t)TT * HID];
__device__ __nv_bfloat16 g_w1_hi [(size_t)QKVN * HID];
__device__ __nv_bfloat16 g_w1_lo [(size_t)QKVN * HID];
__device__ __nv_bfloat16 g_ow_hi [(size_t)HID * HID];
__device__ __nv_bfloat16 g_ow_lo [(size_t)HID * HID];
__device__ __nv_bfloat16 g_at_hi [(size_t)TT * HID];
__device__ __nv_bfloat16 g_at_lo [(size_t)TT * HID];

// bf16 hi/lo Q/K/V for tensor-core attention
__device__ __nv_bfloat16 g_qh[(size_t)TT * NH * HD];
__device__ __nv_bfloat16 g_ql[(size_t)TT * NH * HD];
__device__ __nv_bfloat16 g_kh[(size_t)TT * NKV * HD];
__device__ __nv_bfloat16 g_kl[(size_t)TT * NKV * HD];
__device__ __nv_bfloat16 g_vh[(size_t)TT * NKV * HD];
__device__ __nv_bfloat16 g_vl[(size_t)TT * NKV * HD];

// ======================== helpers ========================
__device__ __forceinline__ uint32_t smem_u32(const void* p) {
    uint32_t a;
    asm("{ .reg .u64 t; cvta.to.shared.u64 t, %1; cvt.u32.u64 %0, t; }"
        : "=r"(a) : "l"(p));
    return a;
}
__device__ __forceinline__ void ldmx4(uint32_t addr, uint32_t& r0, uint32_t& r1,
                                      uint32_t& r2, uint32_t& r3) {
    asm volatile("ldmatrix.sync.aligned.m8n8.x4.shared.b16 {%0,%1,%2,%3}, [%4];"
                 : "=r"(r0), "=r"(r1), "=r"(r2), "=r"(r3) : "r"(addr));
}
__device__ __forceinline__ void ldmx4t(uint32_t addr, uint32_t& r0, uint32_t& r1,
                                       uint32_t& r2, uint32_t& r3) {
    asm volatile("ldmatrix.sync.aligned.m8n8.x4.trans.shared.b16 {%0,%1,%2,%3}, [%4];"
                 : "=r"(r0), "=r"(r1), "=r"(r2), "=r"(r3) : "r"(addr));
}
__device__ __forceinline__ void mma16816(float* c, const uint32_t* a,
                                         uint32_t b0, uint32_t b1) {
    asm volatile(
        "mma.sync.aligned.m16n8k16.row.col.f32.bf16.bf16.f32 "
        "{%0,%1,%2,%3}, {%4,%5,%6,%7}, {%8,%9}, {%0,%1,%2,%3};"
        : "+f"(c[0]), "+f"(c[1]), "+f"(c[2]), "+f"(c[3])
        : "r"(a[0]), "r"(a[1]), "r"(a[2]), "r"(a[3]), "r"(b0), "r"(b1));
}
__device__ __forceinline__ void cpa16(uint32_t dst, const void* src) {
    asm volatile("cp.async.cg.shared.global [%0], [%1], 16;"
                 :: "r"(dst), "l"(src) : "memory");
}
// pack two fp32 into bf16x2: low half = e0, high half = e1
__device__ __forceinline__ uint32_t packbf16(float e0, float e1) {
    uint32_t r;
    asm("cvt.rn.bf16x2.f32 %0, %1, %2;" : "=r"(r) : "f"(e1), "f"(e0));
    return r;
}
__device__ __forceinline__ void split2(float e0, float e1, uint32_t& hi, uint32_t& lo) {
    float h0 = __bfloat162float(__float2bfloat16(e0));
    float h1 = __bfloat162float(__float2bfloat16(e1));
    hi = packbf16(h0, h1);
    lo = packbf16(e0 - h0, e1 - h1);
}

// ======================================================================
// fp32 -> bf16 hi/lo split (8 floats per thread)
// ======================================================================
__global__ __launch_bounds__(256) void cvt_hilo(
    const float* __restrict__ x, __nv_bfloat16* __restrict__ hi,
    __nv_bfloat16* __restrict__ lo, int n8)
{
    int i = blockIdx.x * 256 + threadIdx.x;
    if (i >= n8) return;
    float4 a = ((const float4*)x)[i * 2];
    float4 b = ((const float4*)x)[i * 2 + 1];
    float v[8] = {a.x, a.y, a.z, a.w, b.x, b.y, b.z, b.w};
    __nv_bfloat16 h[8], l[8];
    #pragma unroll
    for (int k = 0; k < 8; k++) {
        h[k] = __float2bfloat16(v[k]);
        l[k] = __float2bfloat16(v[k] - __bfloat162float(h[k]));
    }
    *(uint4*)(hi + (size_t)i * 8) = *(uint4*)h;
    *(uint4*)(lo + (size_t)i * 8) = *(uint4*)l;
}

// V slice (strided inside qkv) -> contiguous bf16 hi/lo [T][NKV][HD]
__global__ __launch_bounds__(256) void cvt_v(
    const float* __restrict__ qkv,
    __nv_bfloat16* __restrict__ hi, __nv_bfloat16* __restrict__ lo)
{
    int i = blockIdx.x * 256 + threadIdx.x;      // float4 index
    const int n4 = TT * NKV * HD / 4;
    if (i >= n4) return;
    int idx = i * 4;
    int row = idx / HD;                          // t*NKV + kv
    int d   = idx % HD;
    int t = row / NKV, kv = row % NKV;
    float4 v = *(const float4*)(qkv + (size_t)t * QKVN + (NH + NKV) * HD + kv * HD + d);
    float e[4] = {v.x, v.y, v.z, v.w};
    __nv_bfloat16 h[4], l[4];
    #pragma unroll
    for (int k = 0; k < 4; k++) {
        h[k] = __float2bfloat16(e[k]);
        l[k] = __float2bfloat16(e[k] - __bfloat162float(h[k]));
    }
    *(uint2*)(hi + idx) = *(uint2*)h;
    *(uint2*)(lo + idx) = *(uint2*)l;
}

// ======================================================================
// HMMA bf16-split GEMM — ROUND-7 VERSION (measured 352us): 256 threads,
// 8 warps x (64x32), register-staged prefetch, double-buffered smem.
// ======================================================================
#define KCH    32
#define ROWB   80
#define MATB   (128 * ROWB)
#define BUFB   (4 * MATB)

__global__ __launch_bounds__(256, 1) void gemm_hmma(
    const __nv_bfloat16* __restrict__ Ahi, const __nv_bfloat16* __restrict__ Alo,
    const __nv_bfloat16* __restrict__ Bhi, const __nv_bfloat16* __restrict__ Blo,
    float* __restrict__ C, int N, int K)
{
    extern __shared__ char smem[];
    const uint32_t sb = smem_u32(smem);
    const int tid  = threadIdx.x;
    const int wid  = tid >> 5;
    const int lane = tid & 31;
    const int bm   = blockIdx.y * 128;
    const int bn   = blockIdx.x * 128;
    const int wm   = wid & 1;
    const int wn   = wid >> 1;

    const int r  = tid >> 1;
    const int ch = (tid & 1) * 16;
    const __nv_bfloat16* src[4] = {
        Ahi + (size_t)(bm + r) * K + ch,
        Alo + (size_t)(bm + r) * K + ch,
        Bhi + (size_t)(bn + r) * K + ch,
        Blo + (size_t)(bn + r) * K + ch };
    const uint32_t stoff = (uint32_t)(r * ROWB + ch * 2);

    const uint32_t arow = (uint32_t)((lane & 7) + ((lane & 8) ? 8 : 0));
    const uint32_t akb  = (lane & 16) ? 16u : 0u;
    const uint32_t brow = (uint32_t)((lane & 7) + ((lane & 16) ? 8 : 0));
    const uint32_t bkb  = (lane & 8) ? 16u : 0u;

    float acc[4][4][4];
    #pragma unroll
    for (int i = 0; i < 4; i++)
        #pragma unroll
        for (int j = 0; j < 4; j++)
            #pragma unroll
            for (int q = 0; q < 4; q++) acc[i][j][q] = 0.f;

    {
        #pragma unroll
        for (int m4 = 0; m4 < 4; m4++) {
            uint4 v0 = *(const uint4*)(src[m4]);
            uint4 v1 = *(const uint4*)(src[m4] + 8);
            *(uint4*)(smem + m4 * MATB + stoff)      = v0;
            *(uint4*)(smem + m4 * MATB + stoff + 16) = v1;
        }
    }
    __syncthreads();

    const int nchunks = K / KCH;
    int cur = 0;
    for (int c = 0; c < nchunks; c++) {
        uint4 v[8];
        const bool have_next = (c + 1 < nchunks);
        if (have_next) {
            const int k0 = (c + 1) * KCH;
            #pragma unroll
            for (int m4 = 0; m4 < 4; m4++) {
                v[m4 * 2]     = *(const uint4*)(src[m4] + k0);
                v[m4 * 2 + 1] = *(const uint4*)(src[m4] + k0 + 8);
            }
        }

        const uint32_t bufo = sb + (uint32_t)(cur * BUFB);
        #pragma unroll
        for (int ks = 0; ks < 2; ks++) {
            const uint32_t kb = ks * 32;
            uint32_t ahi[4][4], alo[4][4], bhi[4][2], blo[4][2];
            #pragma unroll
            for (int i = 0; i < 4; i++) {
                uint32_t ra = (uint32_t)(wm * 64 + i * 16) + arow;
                uint32_t ao = bufo + ra * ROWB + kb + akb;
                ldmx4(ao,        ahi[i][0], ahi[i][1], ahi[i][2], ahi[i][3]);
                ldmx4(ao + MATB, alo[i][0], alo[i][1], alo[i][2], alo[i][3]);
            }
            #pragma unroll
            for (int jj = 0; jj < 2; jj++) {
                uint32_t rb = (uint32_t)(wn * 32 + jj * 16) + brow;
                uint32_t bo = bufo + 2 * MATB + rb * ROWB + kb + bkb;
                uint32_t r0, r1, r2, r3;
                ldmx4(bo, r0, r1, r2, r3);
                bhi[jj*2][0] = r0; bhi[jj*2][1] = r1;
                bhi[jj*2+1][0] = r2; bhi[jj*2+1][1] = r3;
                ldmx4(bo + MATB, r0, r1, r2, r3);
                blo[jj*2][0] = r0; blo[jj*2][1] = r1;
                blo[jj*2+1][0] = r2; blo[jj*2+1][1] = r3;
            }
            #pragma unroll
            for (int i = 0; i < 4; i++)
                #pragma unroll
                for (int j = 0; j < 4; j++) {
                    mma16816(acc[i][j], ahi[i], bhi[j][0], bhi[j][1]);
                    mma16816(acc[i][j], ahi[i], blo[j][0], blo[j][1]);
                    mma16816(acc[i][j], alo[i], bhi[j][0], bhi[j][1]);
                }
        }

        if (have_next) {
            const int nb = cur ^ 1;
            #pragma unroll
            for (int m4 = 0; m4 < 4; m4++) {
                *(uint4*)(smem + nb * BUFB + m4 * MATB + stoff)      = v[m4 * 2];
                *(uint4*)(smem + nb * BUFB + m4 * MATB + stoff + 16) = v[m4 * 2 + 1];
            }
            __syncthreads();
            cur = nb;
        }
    }

    const int er = lane >> 2;
    const int ec = (lane & 3) * 2;
    #pragma unroll
    for (int i = 0; i < 4; i++) {
        const int row0 = bm + wm * 64 + i * 16 + er;
        #pragma unroll
        for (int j = 0; j < 4; j++) {
            const int col = bn + wn * 32 + j * 8 + ec;
            *(float2*)&C[(size_t)row0 * N + col]       = make_float2(acc[i][j][0], acc[i][j][1]);
            *(float2*)&C[(size_t)(row0 + 8) * N + col] = make_float2(acc[i][j][2], acc[i][j][3]);
        }
    }
}

// ======================================================================
// RMSNorm + RoPE -> bf16 hi/lo Q (pre-scaled) and K. One warp per slot.
// ======================================================================
__global__ __launch_bounds__(128) void norm_rope(
    const int* __restrict__ positions,
    const float* __restrict__ qw, const float* __restrict__ kw)
{
    const int slot = blockIdx.x * 4 + (threadIdx.x >> 5);
    const int lane = threadIdx.x & 31;
    const int t  = slot / (NH + NKV);
    const int hh = slot % (NH + NKV);
    const bool isq = hh < NH;

    const float* x = g_qkv + (size_t)t * QKVN +
                     (isq ? hh * HD : NH * HD + (hh - NH) * HD);

    float v0 = x[lane];
    float v1 = x[lane + 32];
    float v2 = x[lane + 64];
    float v3 = x[lane + 96];

    float ss = v0*v0 + v1*v1 + v2*v2 + v3*v3;
    #pragma unroll
    for (int o = 16; o; o >>= 1) ss += __shfl_xor_sync(0xffffffffu, ss, o);

    float rr = rsqrtf(ss * (1.0f / HD) + 1e-6f);
    const float* w = isq ? qw : kw;
    float x0 = v0 * rr * w[lane];
    float x1 = v1 * rr * w[lane + 32];
    float x2 = v2 * rr * w[lane + 64];
    float x3 = v3 * rr * w[lane + 96];

    const float pos = (float)positions[t];
    float f0 = 1.0f / powf(1000000.0f, (float)lane        * (1.0f / 64.0f));
    float f1 = 1.0f / powf(1000000.0f, (float)(lane + 32) * (1.0f / 64.0f));
    float s0, c0, s1, c1;
    sincosf(pos * f0, &s0, &c0);
    sincosf(pos * f1, &s1, &c1);

    const float sc = isq ? 0.08838834764831845f : 1.0f;   // fold softmax scale into Q
    float o0 = (x0 * c0 - x2 * s0) * sc;
    float o1 = (x1 * c1 - x3 * s1) * sc;
    float o2 = (x2 * c0 + x0 * s0) * sc;
    float o3 = (x3 * c1 + x1 * s1) * sc;

    size_t base = isq ? ((size_t)t * NH + hh) * HD
                      : ((size_t)t * NKV + (hh - NH)) * HD;
    __nv_bfloat16* dh = isq ? g_qh + base : g_kh + base;
    __nv_bfloat16* dl = isq ? g_ql + base : g_kl + base;

    float vv[4] = {o0, o1, o2, o3};
    int   dd[4] = {lane, lane + 32, lane + 64, lane + 96};
    #pragma unroll
    for (int k = 0; k < 4; k++) {
        __nv_bfloat16 h = __float2bfloat16(vv[k]);
        dh[dd[k]] = h;
        dl[dd[k]] = __float2bfloat16(vv[k] - __bfloat162float(h));
    }
}

// ======================================================================
// Tensor-core causal GQA flash attention, KV-pipelined (round 13).
// - Q fragments held in registers (loaded once); Q's smem slot becomes
//   the second K buffer -> same 104KB footprint, 2 CTAs/SM.
// - K_{kt+1} prefetched at iter top (hidden behind S+softmax+PV);
//   V_{kt+1} prefetched after PV (hidden behind next S phase).
// - Epilogue writes bf16 hi/lo directly (fuses the O-proj cvt).
// smem layout: [KH0|KL0][VH|VL][KH1|KL1], each tile 64x272B = 17408B.
// ======================================================================
#define AK   17408
#define AMAT (6 * AK)

__global__ __launch_bounds__(128, 2) void attn_mma(
    const __nv_bfloat16* __restrict__ Qh, const __nv_bfloat16* __restrict__ Ql,
    const __nv_bfloat16* __restrict__ Kh, const __nv_bfloat16* __restrict__ Kl,
    const __nv_bfloat16* __restrict__ Vh, const __nv_bfloat16* __restrict__ Vl,
    __nv_bfloat16* __restrict__ at_hi, __nv_bfloat16* __restrict__ at_lo)
{
    extern __shared__ char sm[];
    const uint32_t s0  = smem_u32(sm);
    const uint32_t sVH = s0 + 2 * AK, sVL = s0 + 3 * AK;

    const int h    = blockIdx.y;
    const int qb   = (int)gridDim.x - 1 - (int)blockIdx.x;  // heavy blocks first
    const int kvh  = h >> 1;
    const int tid  = threadIdx.x;
    const int wq   = tid >> 5;
    const int lane = tid & 31;

    const int cr  = tid >> 1;                       // copy row 0..63
    const int chf = tid & 1;                        // col half (128 bytes)
    const uint32_t doff = (uint32_t)(cr * 272 + chf * 128);

    // per-lane ldmatrix offsets (within one 64x272B tile)
    const uint32_t qoffm = (uint32_t)((wq * 16 + (lane & 15)) * 272 + ((lane & 16) ? 16 : 0));
    const uint32_t koffm = (uint32_t)((((lane & 7) + ((lane & 16) ? 8 : 0))) * 272 + ((lane & 8) ? 16 : 0));
    const uint32_t voffm = (uint32_t)((((lane & 7) + ((lane & 8) ? 8 : 0))) * 272 + ((lane & 16) ? 16 : 0));

    // ---- prologue: Q -> smem (in the bufK1 slot), then into registers ----
    {
        size_t qoff = ((size_t)(qb * 64 + cr) * NH + h) * HD + chf * 64;
        #pragma unroll
        for (int u = 0; u < 8; u++) {
            cpa16(s0 + 4 * AK + doff + u * 16, Qh + qoff + u * 8);
            cpa16(s0 + 5 * AK + doff + u * 16, Ql + qoff + u * 8);
        }
    }
    asm volatile("cp.async.commit_group;");
    asm volatile("cp.async.wait_group 0;");
    __syncthreads();

    uint32_t qfh[8][4], qfl[8][4];
    #pragma unroll
    for (int ks = 0; ks < 8; ks++) {
        ldmx4(s0 + 4 * AK + qoffm + ks * 32, qfh[ks][0], qfh[ks][1], qfh[ks][2], qfh[ks][3]);
        ldmx4(s0 + 5 * AK + qoffm + ks * 32, qfl[ks][0], qfl[ks][1], qfl[ks][2], qfl[ks][3]);
    }
    __syncthreads();   // all warps done reading Q smem before it becomes bufK1

    // ---- prologue loads: K0 (group), V0 (group) ----
    {
        size_t base = ((size_t)(0 * 64 + cr) * NKV + kvh) * HD + chf * 64;
        #pragma unroll
        for (int u = 0; u < 8; u++) {
            cpa16(s0 + doff + u * 16,      Kh + base + u * 8);
            cpa16(s0 + AK + doff + u * 16, Kl + base + u * 8);
        }
        asm volatile("cp.async.commit_group;");
        #pragma unroll
        for (int u = 0; u < 8; u++) {
            cpa16(sVH + doff + u * 16, Vh + base + u * 8);
            cpa16(sVL + doff + u * 16, Vl + base + u * 8);
        }
        asm volatile("cp.async.commit_group;");
    }

    float O[16][4];
    #pragma unroll
    for (int i = 0; i < 16; i++)
        #pragma unroll
        for (int q = 0; q < 4; q++) O[i][q] = 0.f;
    float m0 = -1e30f, m1 = -1e30f, l0 = 0.f, l1 = 0.f;

    const int r0 = lane >> 2;
    const int c0 = (lane & 3) * 2;

    for (int kt = 0; kt <= qb; kt++) {
        // K_kt ready (leave the newest group — V_kt or K_{kt+1} chain — pending)
        asm volatile("cp.async.wait_group 1;");
        __syncthreads();

        // prefetch K_{kt+1} into the other K buffer
        if (kt < qb) {
            size_t nbase = ((size_t)((kt + 1) * 64 + cr) * NKV + kvh) * HD + chf * 64;
            uint32_t kb = s0 + (uint32_t)(((kt + 1) & 1) * (4 * AK));
            #pragma unroll
            for (int u = 0; u < 8; u++) {
                cpa16(kb + doff + u * 16,      Kh + nbase + u * 8);
                cpa16(kb + AK + doff + u * 16, Kl + nbase + u * 8);
            }
            asm volatile("cp.async.commit_group;");
        }

        const uint32_t kbc = s0 + (uint32_t)((kt & 1) * (4 * AK));

        // ---- scores S[64q x 64j] per warp: 16 x 64 ----
        float S[8][4];
        #pragma unroll
        for (int i = 0; i < 8; i++)
            #pragma unroll
            for (int q = 0; q < 4; q++) S[i][q] = 0.f;

        #pragma unroll
        for (int ks = 0; ks < 8; ks++) {
            #pragma unroll
            for (int g = 0; g < 4; g++) {
                uint32_t ka = kbc + koffm + g * (16 * 272) + ks * 32;
                uint32_t kh0, kh1, kh2, kh3, kl0, kl1, kl2, kl3;
                ldmx4(ka,      kh0, kh1, kh2, kh3);
                ldmx4(ka + AK, kl0, kl1, kl2, kl3);
                mma16816(S[2*g],     qfh[ks], kh0, kh1);
                mma16816(S[2*g],     qfh[ks], kl0, kl1);
                mma16816(S[2*g],     qfl[ks], kh0, kh1);
                mma16816(S[2*g + 1], qfh[ks], kh2, kh3);
                mma16816(S[2*g + 1], qfh[ks], kl2, kl3);
                mma16816(S[2*g + 1], qfl[ks], kh2, kh3);
            }
        }

        // ---- causal mask (diagonal block only) ----
        if (kt == qb) {
            const int ra = wq * 16 + r0, rb = ra + 8;
            #pragma unroll
            for (int nt = 0; nt < 8; nt++) {
                int j = nt * 8 + c0;
                if (j     > ra) S[nt][0] = -1e30f;
                if (j + 1 > ra) S[nt][1] = -1e30f;
                if (j     > rb) S[nt][2] = -1e30f;
                if (j + 1 > rb) S[nt][3] = -1e30f;
            }
        }

        // ---- online softmax ----
        float mt0 = -1e30f, mt1 = -1e30f;
        #pragma unroll
        for (int nt = 0; nt < 8; nt++) {
            mt0 = fmaxf(mt0, fmaxf(S[nt][0], S[nt][1]));
            mt1 = fmaxf(mt1, fmaxf(S[nt][2], S[nt][3]));
        }
        mt0 = fmaxf(mt0, __shfl_xor_sync(0xffffffffu, mt0, 1));
        mt0 = fmaxf(mt0, __shfl_xor_sync(0xffffffffu, mt0, 2));
        mt1 = fmaxf(mt1, __shfl_xor_sync(0xffffffffu, mt1, 1));
        mt1 = fmaxf(mt1, __shfl_xor_sync(0xffffffffu, mt1, 2));

        float mn0 = fmaxf(m0, mt0), mn1 = fmaxf(m1, mt1);
        float al0 = __expf(m0 - mn0), al1 = __expf(m1 - mn1);
        m0 = mn0; m1 = mn1;

        float s0r = 0.f, s1r = 0.f;
        #pragma unroll
        for (int nt = 0; nt < 8; nt++) {
            S[nt][0] = __expf(S[nt][0] - mn0); s0r += S[nt][0];
            S[nt][1] = __expf(S[nt][1] - mn0); s0r += S[nt][1];
            S[nt][2] = __expf(S[nt][2] - mn1); s1r += S[nt][2];
            S[nt][3] = __expf(S[nt][3] - mn1); s1r += S[nt][3];
        }
        s0r += __shfl_xor_sync(0xffffffffu, s0r, 1);
        s0r += __shfl_xor_sync(0xffffffffu, s0r, 2);
        s1r += __shfl_xor_sync(0xffffffffu, s1r, 1);
        s1r += __shfl_xor_sync(0xffffffffu, s1r, 2);
        l0 = l0 * al0 + s0r;
        l1 = l1 * al1 + s1r;

        #pragma unroll
        for (int nd = 0; nd < 16; nd++) {
            O[nd][0] *= al0; O[nd][1] *= al0;
            O[nd][2] *= al1; O[nd][3] *= al1;
        }

        // ---- V_kt ready (leave K_{kt+1} pending if it exists) ----
        if (kt < qb) { asm volatile("cp.async.wait_group 1;"); }
        else         { asm volatile("cp.async.wait_group 0;"); }
        __syncthreads();

        // ---- PV: O[16 x 128] += P[16 x 64] * V[64 x 128] ----
        #pragma unroll
        for (int g = 0; g < 4; g++) {
            uint32_t ph[4], pl[4];
            split2(S[2*g][0],     S[2*g][1],     ph[0], pl[0]);
            split2(S[2*g][2],     S[2*g][3],     ph[1], pl[1]);
            split2(S[2*g + 1][0], S[2*g + 1][1], ph[2], pl[2]);
            split2(S[2*g + 1][2], S[2*g + 1][3], ph[3], pl[3]);
            #pragma unroll
            for (int db = 0; db < 8; db++) {
                uint32_t va = voffm + g * (16 * 272) + db * 32;
                uint32_t vh0, vh1, vh2, vh3, vl0, vl1, vl2, vl3;
                ldmx4t(sVH + va, vh0, vh1, vh2, vh3);
                ldmx4t(sVL + va, vl0, vl1, vl2, vl3);
                mma16816(O[2*db],     ph, vh0, vh1);
                mma16816(O[2*db],     ph, vl0, vl1);
                mma16816(O[2*db],     pl, vh0, vh1);
                mma16816(O[2*db + 1], ph, vh2, vh3);
                mma16816(O[2*db + 1], ph, vl2, vl3);
                mma16816(O[2*db + 1], pl, vh2, vh3);
            }
        }

        // ---- prefetch V_{kt+1} (all warps done reading V_kt) ----
        __syncthreads();
        if (kt < qb) {
            size_t nbase = ((size_t)((kt + 1) * 64 + cr) * NKV + kvh) * HD + chf * 64;
            #pragma unroll
            for (int u = 0; u < 8; u++) {
                cpa16(sVH + doff + u * 16, Vh + nbase + u * 8);
                cpa16(sVL + doff + u * 16, Vl + nbase + u * 8);
            }
            asm volatile("cp.async.commit_group;");
        }
    }

    // ---- write out: bf16 hi/lo directly (fused O-proj cvt) ----
    const float i0 = 1.f / l0, i1 = 1.f / l1;
    const int qg = qb * 64 + wq * 16;
    const size_t rowA = (size_t)(qg + r0)     * HID;
    const size_t rowB = (size_t)(qg + r0 + 8) * HID;
    #pragma unroll
    for (int nd = 0; nd < 16; nd++) {
        const int col = h * 128 + nd * 8 + c0;
        uint32_t ha, la, hb, lb;
        split2(O[nd][0] * i0, O[nd][1] * i0, ha, la);
        split2(O[nd][2] * i1, O[nd][3] * i1, hb, lb);
        *(uint32_t*)(at_hi + rowA + col) = ha;
        *(uint32_t*)(at_lo + rowA + col) = la;
        *(uint32_t*)(at_hi + rowB + col) = hb;
        *(uint32_t*)(at_lo + rowB + col) = lb;
    }
}

// ======================================================================
// launch — inputs bound by element count (order-agnostic)
// ======================================================================
extern "C" void kernel_launch(void* const* d_in, const int* in_sizes, int n_in,
                              void* d_out, int out_size)
{
    const float* hidden    = 0;
    const int*   positions = 0;
    const float* qkv_w     = 0;
    const float* o_w       = 0;
    const float* qw        = 0;
    const float* kw        = 0;

    for (int i = 0; i < n_in; i++) {
        int s = in_sizes[i];
        if (s == QKVN * HID)            qkv_w = (const float*)d_in[i];
        else if (s == TT * HID) {
            if (!hidden) hidden = (const float*)d_in[i];
            else         o_w    = (const float*)d_in[i];
        }
        else if (s == TT)               positions = (const int*)d_in[i];
        else if (s == HD) {
            if (!qw) qw = (const float*)d_in[i];
            else     kw = (const float*)d_in[i];
        }
    }
    if (!kw) kw = qw;

    float* out = (float*)d_out;

    float* qkv_p;
    cudaGetSymbolAddress((void**)&qkv_p, g_qkv);
    __nv_bfloat16 *hid_hi, *hid_lo, *w1_hi, *w1_lo, *ow_hi, *ow_lo, *at_hi, *at_lo;
    __nv_bfloat16 *qh, *ql, *kh, *kl, *vh, *vl;
    cudaGetSymbolAddress((void**)&hid_hi, g_hid_hi);
    cudaGetSymbolAddress((void**)&hid_lo, g_hid_lo);
    cudaGetSymbolAddress((void**)&w1_hi,  g_w1_hi);
    cudaGetSymbolAddress((void**)&w1_lo,  g_w1_lo);
    cudaGetSymbolAddress((void**)&ow_hi,  g_ow_hi);
    cudaGetSymbolAddress((void**)&ow_lo,  g_ow_lo);
    cudaGetSymbolAddress((void**)&at_hi,  g_at_hi);
    cudaGetSymbolAddress((void**)&at_lo,  g_at_lo);
    cudaGetSymbolAddress((void**)&qh, g_qh);
    cudaGetSymbolAddress((void**)&ql, g_ql);
    cudaGetSymbolAddress((void**)&kh, g_kh);
    cudaGetSymbolAddress((void**)&kl, g_kl);
    cudaGetSymbolAddress((void**)&vh, g_vh);
    cudaGetSymbolAddress((void**)&vl, g_vl);

    const int gemm_smem = 2 * BUFB;          // 81920
    cudaFuncSetAttribute(gemm_hmma,
                         cudaFuncAttributeMaxDynamicSharedMemorySize, gemm_smem);
    const int attn_smem = AMAT;              // 104448
    cudaFuncSetAttribute(attn_mma,
                         cudaFuncAttributeMaxDynamicSharedMemorySize, attn_smem);

    // 0. hi/lo splits of GEMM operands
    cvt_hilo<<<(TT * HID / 8 + 255) / 256, 256>>>(hidden, hid_hi, hid_lo, TT * HID / 8);
    cvt_hilo<<<(QKVN * HID / 8 + 255) / 256, 256>>>(qkv_w, w1_hi, w1_lo, QKVN * HID / 8);
    cvt_hilo<<<(HID * HID / 8 + 255) / 256, 256>>>(o_w, ow_hi, ow_lo, HID * HID / 8);

    // 1. QKV projection (HMMA, round-7 config)
    gemm_hmma<<<dim3(QKVN / 128, TT / 128), 256, gemm_smem>>>(
        hid_hi, hid_lo, w1_hi, w1_lo, qkv_p, QKVN, HID);

    // 2. RMSNorm + RoPE -> bf16 hi/lo Q,K ; V split
    norm_rope<<<TT * (NH + NKV) / 4, 128>>>(positions, qw, kw);
    cvt_v<<<(TT * NKV * HD / 4 + 255) / 256, 256>>>(qkv_p, vh, vl);

    // 3. Tensor-core causal attention (KV-pipelined, fused hi/lo epilogue)
    attn_mma<<<dim3(TT / 64, NH), 128, attn_smem>>>(qh, ql, kh, kl, vh, vl, at_hi, at_lo);

    // 4. Output projection (HMMA)
    gemm_hmma<<<dim3(HID / 128, TT / 128), 256, gemm_smem>>>(
        at_hi, at_lo, ow_hi, ow_lo, out, HID, HID);
}